// round 2
// baseline (speedup 1.0000x reference)
#include <cuda_runtime.h>

#define EPSF 1e-5f
#define HW   16384
#define CHW  2097152   /* 128*128*128 */

// ---------------- scratch (static device memory; no allocation) ----------------
__device__ float g_xp [8*CHW];
__device__ float g_x1 [8*CHW];
__device__ float g_x2 [8*CHW];
__device__ float g_xfp[8*CHW];
__device__ float g_xrp[8*CHW];
__device__ float g_cat[8*384*HW];   // (b, 3c, h, w)

// =============================================================================
// conv1x1:  Y[b,o,p] = sum_c W[o,c] * X[b,c,p] + bias[o]
// CTA: one batch b, 128-pixel tile. 256 thr, 8x8 micro-tile (strided mapping).
// smem: Ws [c][132] (o-major rows, transposed), Xs [c][128].
// =============================================================================
__global__ __launch_bounds__(256) void conv1x1_kernel(
    const float* __restrict__ X, const float* __restrict__ Wm,
    const float* __restrict__ bias, float* __restrict__ Y)
{
    extern __shared__ float sm[];
    float* Ws = sm;              // 128*132
    float* Xs = sm + 128*132;    // 128*128
    const int tid = threadIdx.x;
    const int b   = blockIdx.y;
    const int p0  = blockIdx.x << 7;

    for (int idx = tid; idx < 128*128; idx += 256) {
        int o = idx >> 7, c = idx & 127;
        Ws[c*132 + o] = Wm[idx];
    }
    const float4* Xg = (const float4*)(X + (size_t)b*CHW + p0);
    for (int idx = tid; idx < 128*32; idx += 256) {
        int c = idx >> 5, q = idx & 31;
        float4 v = Xg[c*(HW>>2) + q];
        *((float4*)(Xs + c*128) + q) = v;
    }
    __syncthreads();

    const int tx = tid & 15, ty = tid >> 4;
    float acc[8][8];
#pragma unroll
    for (int i = 0; i < 8; i++)
#pragma unroll
        for (int j = 0; j < 8; j++) acc[i][j] = 0.f;

#pragma unroll 4
    for (int c = 0; c < 128; c++) {
        float a[8], x[8];
#pragma unroll
        for (int i = 0; i < 8; i++) a[i] = Ws[c*132 + ty + 16*i];
#pragma unroll
        for (int j = 0; j < 8; j++) x[j] = Xs[c*128 + tx + 16*j];
#pragma unroll
        for (int i = 0; i < 8; i++)
#pragma unroll
            for (int j = 0; j < 8; j++) acc[i][j] = fmaf(a[i], x[j], acc[i][j]);
    }

#pragma unroll
    for (int i = 0; i < 8; i++) {
        int o = ty + 16*i;
        float bo = bias[o];
        float* Yp = Y + (size_t)b*CHW + (size_t)o*HW + p0 + tx;
#pragma unroll
        for (int j = 0; j < 8; j++) Yp[16*j] = acc[i][j] + bo;
    }
}

// =============================================================================
// block reduction: sum + sumsq over 256 threads
// =============================================================================
__device__ __forceinline__ void block_reduce_2(float& s, float& q, float* red)
{
#pragma unroll
    for (int off = 16; off > 0; off >>= 1) {
        s += __shfl_down_sync(0xffffffffu, s, off);
        q += __shfl_down_sync(0xffffffffu, q, off);
    }
    const int wid = threadIdx.x >> 5;
    if ((threadIdx.x & 31) == 0) { red[wid] = s; red[8 + wid] = q; }
    __syncthreads();
    s = 0.f; q = 0.f;
#pragma unroll
    for (int i = 0; i < 8; i++) { s += red[i]; q += red[8 + i]; }
    __syncthreads();
}

// =============================================================================
// Attention: one CTA per (h, b, branch).
//   S[c][d]  = sum_w P[b,c,h,w]*Qp[b,d,h,w]   (P=x1|x2, Qp=xfp|xrp)
//   S <- inorm(S);  F[c][w] = sum_d S[c][d]*xp[b,d,h,w];  F <- inorm(F)
//   cat[b, br*128 + c, h, w] = F[c][w]
// =============================================================================
__global__ __launch_bounds__(256) void attn_kernel()
{
    extern __shared__ float sm[];
    float* bufA = sm;               // [128][129]
    float* bufB = sm + 128*129;     // [128][129]
    __shared__ float red[16];

    const int h = blockIdx.x, b = blockIdx.y, br = blockIdx.z;
    const float* P = br ? g_x2  : g_x1;
    const float* Q = br ? g_xrp : g_xfp;
    const int tid = threadIdx.x, tx = tid & 15, ty = tid >> 4;
    const size_t base = (size_t)b*CHW + (size_t)h*128;

    for (int idx = tid; idx < 128*32; idx += 256) {
        int r = idx >> 5, q = idx & 31;
        float4 v = *(const float4*)(P + base + (size_t)r*HW + 4*q);
        float* d0 = bufA + r*129 + 4*q;
        d0[0]=v.x; d0[1]=v.y; d0[2]=v.z; d0[3]=v.w;
        float4 u = *(const float4*)(Q + base + (size_t)r*HW + 4*q);
        float* e0 = bufB + r*129 + 4*q;
        e0[0]=u.x; e0[1]=u.y; e0[2]=u.z; e0[3]=u.w;
    }
    __syncthreads();

    // GEMM1: S = P * Q^T   (thread tile c = ty+16i, d = tx+16j)
    float s[8][8];
#pragma unroll
    for (int i=0;i<8;i++)
#pragma unroll
        for (int j=0;j<8;j++) s[i][j]=0.f;
#pragma unroll 4
    for (int w = 0; w < 128; w++) {
        float a[8], bb[8];
#pragma unroll
        for (int i=0;i<8;i++) a[i]  = bufA[(ty+16*i)*129 + w];
#pragma unroll
        for (int j=0;j<8;j++) bb[j] = bufB[(tx+16*j)*129 + w];
#pragma unroll
        for (int i=0;i<8;i++)
#pragma unroll
            for (int j=0;j<8;j++) s[i][j] = fmaf(a[i], bb[j], s[i][j]);
    }

    // instance norm of S over all 16384 values
    float ls = 0.f, lq = 0.f;
#pragma unroll
    for (int i=0;i<8;i++)
#pragma unroll
        for (int j=0;j<8;j++) { ls += s[i][j]; lq += s[i][j]*s[i][j]; }
    block_reduce_2(ls, lq, red);
    float mean = ls * (1.f/16384.f);
    float var  = lq * (1.f/16384.f) - mean*mean;
    float inv  = rsqrtf(var + EPSF);

    // restage: bufA <- S^T (Sd[d][c]), bufB <- xp tile   (reduce's sync covers hazards)
#pragma unroll
    for (int i=0;i<8;i++)
#pragma unroll
        for (int j=0;j<8;j++)
            bufA[(tx+16*j)*129 + (ty+16*i)] = (s[i][j]-mean)*inv;
    for (int idx = tid; idx < 128*32; idx += 256) {
        int r = idx >> 5, q = idx & 31;
        float4 v = *(const float4*)(g_xp + base + (size_t)r*HW + 4*q);
        float* e0 = bufB + r*129 + 4*q;
        e0[0]=v.x; e0[1]=v.y; e0[2]=v.z; e0[3]=v.w;
    }
    __syncthreads();

    // GEMM2: F[c][w] = sum_d Sd[d][c] * Xp[d][w]
    float f[8][8];
#pragma unroll
    for (int i=0;i<8;i++)
#pragma unroll
        for (int j=0;j<8;j++) f[i][j]=0.f;
#pragma unroll 4
    for (int d = 0; d < 128; d++) {
        float a[8], bb[8];
#pragma unroll
        for (int i=0;i<8;i++) a[i]  = bufA[d*129 + ty + 16*i];
#pragma unroll
        for (int j=0;j<8;j++) bb[j] = bufB[d*129 + tx + 16*j];
#pragma unroll
        for (int i=0;i<8;i++)
#pragma unroll
            for (int j=0;j<8;j++) f[i][j] = fmaf(a[i], bb[j], f[i][j]);
    }

    // instance norm of F
    ls = 0.f; lq = 0.f;
#pragma unroll
    for (int i=0;i<8;i++)
#pragma unroll
        for (int j=0;j<8;j++) { ls += f[i][j]; lq += f[i][j]*f[i][j]; }
    block_reduce_2(ls, lq, red);
    mean = ls * (1.f/16384.f);
    var  = lq * (1.f/16384.f) - mean*mean;
    inv  = rsqrtf(var + EPSF);

    const int co = br << 7;
#pragma unroll
    for (int i=0;i<8;i++) {
        int c = ty + 16*i;
        float* dst = g_cat + ((size_t)b*384 + co + c)*HW + (size_t)h*128 + tx;
#pragma unroll
        for (int j=0;j<8;j++) dst[16*j] = (f[i][j]-mean)*inv;
    }
}

// =============================================================================
// copy x into cat channels 256..383 (contiguous per batch)
// =============================================================================
__global__ void copy_x_kernel(const float* __restrict__ x)
{
    int idx = blockIdx.x*256 + threadIdx.x;           // over 4194304 float4
    int b = idx >> 19;                                 // CHW/4 = 524288
    int r = idx & 524287;
    ((float4*)g_cat)[((size_t)b*384 + 256)*(HW>>2) + r] = ((const float4*)x)[idx];
}

// =============================================================================
// conv3x3 (pad 1) + BN(eval) + ReLU, implicit GEMM.
// CTA: one (b, h) row x 128 o-channels. K loop: ci chunks of 8 x 9 taps.
// smem: Wc [72][132] ([k][o] transposed), Is [8*3][132] input rows with halo.
// =============================================================================
__global__ __launch_bounds__(256) void conv3x3_kernel(
    const float* __restrict__ Wm, const float* __restrict__ bm,
    const float* __restrict__ gamma, const float* __restrict__ beta,
    const float* __restrict__ rmean, const float* __restrict__ rvar,
    float* __restrict__ out)
{
    extern __shared__ float sm[];
    float* Wc = sm;            // 72*132
    float* Is = sm + 72*132;   // 24*132
    const int h  = blockIdx.x;
    const int o0 = blockIdx.y << 7;
    const int b  = blockIdx.z;
    const int tid = threadIdx.x, tx = tid & 15, ty = tid >> 4;

    float acc[8][8];
#pragma unroll
    for (int i=0;i<8;i++)
#pragma unroll
        for (int j=0;j<8;j++) acc[i][j]=0.f;

    const float* catb = g_cat + (size_t)b*384*HW;

    for (int ci0 = 0; ci0 < 384; ci0 += 8) {
        __syncthreads();
        for (int idx = tid; idx < 9216; idx += 256) {        // 128 o x 72 k
            int ol = idx / 72, r = idx - ol*72;
            Wc[r*132 + ol] = Wm[(size_t)(o0+ol)*3456 + ci0*9 + r];
        }
        for (int idx = tid; idx < 8*3*132; idx += 256) {     // input + halo
            int ci = idx / 396, rr = idx - ci*396;
            int row = rr / 132, col = rr - row*132;
            int hh = h + row - 1, w = col - 1;
            float v = 0.f;
            if (((unsigned)hh < 128u) && ((unsigned)w < 128u))
                v = catb[(size_t)(ci0+ci)*HW + hh*128 + w];
            Is[(ci*3+row)*132 + col] = v;
        }
        __syncthreads();

        for (int ci = 0; ci < 8; ci++) {
#pragma unroll
            for (int t = 0; t < 9; t++) {
                const int kh = t/3, kw = t - kh*3;
                float wv[8], iv[8];
#pragma unroll
                for (int i=0;i<8;i++) wv[i] = Wc[(ci*9+t)*132 + ty + 16*i];
#pragma unroll
                for (int j=0;j<8;j++) iv[j] = Is[(ci*3+kh)*132 + tx + 16*j + kw];
#pragma unroll
                for (int i=0;i<8;i++)
#pragma unroll
                    for (int j=0;j<8;j++) acc[i][j] = fmaf(wv[i], iv[j], acc[i][j]);
            }
        }
    }

#pragma unroll
    for (int i=0;i<8;i++) {
        int o = o0 + ty + 16*i;
        float sc = gamma[o] * rsqrtf(rvar[o] + EPSF);
        float sh = beta[o] + (bm[o] - rmean[o]) * sc;
        float* dst = out + ((size_t)b*384 + o)*HW + (size_t)h*128 + tx;
#pragma unroll
        for (int j=0;j<8;j++) {
            float y = fmaf(acc[i][j], sc, sh);
            dst[16*j] = fmaxf(y, 0.f);
        }
    }
}

// =============================================================================
extern "C" void kernel_launch(void* const* d_in, const int* in_sizes, int n_in,
                              void* d_out, int out_size)
{
    const float* x  = (const float*)d_in[0];
    const float* xf = (const float*)d_in[1];
    const float* xr = (const float*)d_in[2];
    const float* Wx = (const float*)d_in[3];
    const float* bx = (const float*)d_in[4];
    const float* W1 = (const float*)d_in[5];
    const float* b1 = (const float*)d_in[6];
    const float* W2 = (const float*)d_in[7];
    const float* b2 = (const float*)d_in[8];
    const float* Wf = (const float*)d_in[9];
    const float* bf = (const float*)d_in[10];
    const float* Wr = (const float*)d_in[11];
    const float* br = (const float*)d_in[12];
    const float* Wm = (const float*)d_in[13];
    const float* bm = (const float*)d_in[14];
    const float* gamma = (const float*)d_in[15];
    const float* beta  = (const float*)d_in[16];
    const float* rmean = (const float*)d_in[17];
    const float* rvar  = (const float*)d_in[18];
    float* out = (float*)d_out;

    void *pxp, *px1, *px2, *pxfp, *pxrp;
    cudaGetSymbolAddress(&pxp,  g_xp);
    cudaGetSymbolAddress(&px1,  g_x1);
    cudaGetSymbolAddress(&px2,  g_x2);
    cudaGetSymbolAddress(&pxfp, g_xfp);
    cudaGetSymbolAddress(&pxrp, g_xrp);

    cudaFuncSetAttribute(conv1x1_kernel, cudaFuncAttributeMaxDynamicSharedMemorySize, 133120);
    cudaFuncSetAttribute(attn_kernel,    cudaFuncAttributeMaxDynamicSharedMemorySize, 132096);
    cudaFuncSetAttribute(conv3x3_kernel, cudaFuncAttributeMaxDynamicSharedMemorySize, 50688);

    dim3 g1(128, 8);
    conv1x1_kernel<<<g1, 256, 133120>>>(x,  Wx, bx, (float*)pxp);
    conv1x1_kernel<<<g1, 256, 133120>>>((const float*)pxp, W1, b1, (float*)px1);
    conv1x1_kernel<<<g1, 256, 133120>>>((const float*)pxp, W2, b2, (float*)px2);
    conv1x1_kernel<<<g1, 256, 133120>>>(xf, Wf, bf, (float*)pxfp);
    conv1x1_kernel<<<g1, 256, 133120>>>(xr, Wr, br, (float*)pxrp);
    copy_x_kernel<<<16384, 256>>>(x);
    attn_kernel<<<dim3(128, 8, 2), 256, 132096>>>();
    conv3x3_kernel<<<dim3(128, 3, 8), 256, 50688>>>(Wm, bm, gamma, beta, rmean, rvar, out);
}